// round 4
// baseline (speedup 1.0000x reference)
#include <cuda_runtime.h>

#define NN 50000
#define NE 800000
#define NG 256
#define DH  64
#define HID 256
#define EPSF 1e-5f
#define SBS 256
#define NBLK ((NN + SBS - 1) / SBS)          // 196
#define NSTRIP 128
#define STRIPN ((NN + NSTRIP - 1) / NSTRIP)  // 391

// ---------------- device scratch ----------------
__device__ float4 g_xl [NN*16];
__device__ float4 g_xr [NN*16];
__device__ float4 g_h  [NN*16];
__device__ float4 g_Wt [6*2048];
__device__ float  g_pool[NG*DH];
__device__ float  g_gcnt[NG];
__device__ float  g_c  [NG*DH];
__device__ float  g_z1 [NG*HID];
__device__ float  g_z2 [NG*(HID/2)];
__device__ float  g_z3 [NG*(HID/4)];
__device__ int    g_src[NE];
__device__ int    g_dst[NE];
__device__ int    g_batch[NN];
__device__ int    g_deg[NN];
__device__ int    g_part[NN];
__device__ int    g_bsum[NBLK];
__device__ int    g_boff[NBLK];
__device__ int    g_rowptr[NN + 1];
__device__ int    g_woff[NN];
__device__ int    g_csr[NE];
__device__ int    g_is64;

// ---------------- kernels ----------------
__global__ void k_zero(float* __restrict__ p, int n) {
    int i = blockIdx.x * blockDim.x + threadIdx.x;
    if (i < n) p[i] = 0.f;
}
__global__ void k_zeroi(int* __restrict__ p, int n) {
    int i = blockIdx.x * blockDim.x + threadIdx.x;
    if (i < n) p[i] = 0;
}

// Detect whether edge_index is int64 or int32.
// If int64 (values < 2^31): odd int32 words (high halves) are all zero.
// If int32: odd words are random node ids in [0, NN) -> ~never all zero.
__global__ void k_detect(const int* __restrict__ e32) {
    if (threadIdx.x == 0 && blockIdx.x == 0) {
        int all0 = 1;
        for (int k = 0; k < 16; k++)
            if (e32[2 * (1000 + k) + 1] != 0) all0 = 0;
        g_is64 = all0;
    }
}

// edge_index (either dtype) -> int32 src/dst + degree histogram (by dst)
__global__ void k_prep(const void* __restrict__ eidx) {
    int e = blockIdx.x * blockDim.x + threadIdx.x;
    if (e >= NE) return;
    int s, d;
    if (g_is64) {
        const long long* p = (const long long*)eidx;
        s = (int)p[e];
        d = (int)p[NE + e];
    } else {
        const int* p = (const int*)eidx;
        s = p[e];
        d = p[NE + e];
    }
    g_src[e] = s;
    g_dst[e] = d;
    atomicAdd(&g_deg[d], 1);
}

// batch (either dtype) -> int32 g_batch
__global__ void k_bconv(const void* __restrict__ batch) {
    int i = blockIdx.x * blockDim.x + threadIdx.x;
    if (i >= NN) return;
    g_batch[i] = g_is64 ? (int)((const long long*)batch)[i]
                        : ((const int*)batch)[i];
}

// block-level inclusive scan -> exclusive-within-block + block sums
__global__ void k_scan1() {
    __shared__ int s[SBS];
    int tid = threadIdx.x;
    int i = blockIdx.x * SBS + tid;
    int v = (i < NN) ? g_deg[i] : 0;
    s[tid] = v;
    __syncthreads();
    for (int off = 1; off < SBS; off <<= 1) {
        int t = (tid >= off) ? s[tid - off] : 0;
        __syncthreads();
        s[tid] += t;
        __syncthreads();
    }
    if (i < NN) g_part[i] = s[tid] - v;
    if (tid == SBS - 1) g_bsum[blockIdx.x] = s[tid];
}

__global__ void k_scan2() {
    if (threadIdx.x == 0 && blockIdx.x == 0) {
        int run = 0;
        for (int b = 0; b < NBLK; b++) {
            g_boff[b] = run;
            run += g_bsum[b];
        }
    }
}

__global__ void k_scan3() {
    int i = blockIdx.x * blockDim.x + threadIdx.x;
    if (i < NN) {
        int r = g_part[i] + g_boff[i / SBS];
        g_rowptr[i] = r;
        g_woff[i]   = r;
    }
    if (i == 0) g_rowptr[NN] = NE;
}

__global__ void k_fill() {
    int e = blockIdx.x * blockDim.x + threadIdx.x;
    if (e >= NE) return;
    int d = g_dst[e];
    int p = atomicAdd(&g_woff[d], 1);
    g_csr[p] = g_src[e];
}

// xl = x @ Wl ; xr = x @ Wr + bl   (4 nodes / 256-thread block)
__global__ void k_dual_gemm(const float* __restrict__ x,
                            const float4* __restrict__ Wl,
                            const float4* __restrict__ Wr,
                            const float* __restrict__ bl, int din) {
    int grp  = threadIdx.x >> 6;
    int node = blockIdx.x * 4 + grp;
    int j    = threadIdx.x & 63;
    __shared__ float xs[4][128];
    for (int k = j; k < din; k += 64) xs[grp][k] = x[node * din + k];
    __syncthreads();
    const float*  row = xs[grp];
    const float4* wl  = Wl + j * (din >> 2);
    const float4* wr  = Wr + j * (din >> 2);
    float sl = 0.f, sr = 0.f;
    int kq = din >> 2;
#pragma unroll 8
    for (int k = 0; k < kq; k++) {
        float4 a = wl[k], b = wr[k];
        float x0 = row[4*k], x1 = row[4*k+1], x2 = row[4*k+2], x3 = row[4*k+3];
        sl = fmaf(a.x, x0, sl); sl = fmaf(a.y, x1, sl);
        sl = fmaf(a.z, x2, sl); sl = fmaf(a.w, x3, sl);
        sr = fmaf(b.x, x0, sr); sr = fmaf(b.y, x1, sr);
        sr = fmaf(b.z, x2, sr); sr = fmaf(b.w, x3, sr);
    }
    ((float*)g_xl)[node * 64 + j] = sl;
    ((float*)g_xr)[node * 64 + j] = sr + bl[j];
}

// CSR gather aggregation: h = mean_in(xl) + xr   (64 threads per node)
__global__ void k_aggr() {
    int node = blockIdx.x * 4 + (threadIdx.x >> 6);
    int j    = threadIdx.x & 63;
    int beg = g_rowptr[node], end = g_rowptr[node + 1];
    const float* xlf = (const float*)g_xl;
    float s = 0.f;
    for (int i = beg; i < end; i++) {
        int u = g_csr[i];
        s += xlf[u * 64 + j];
    }
    float inv = 1.0f / fmaxf((float)(end - beg), 1.0f);
    ((float*)g_h)[node * 64 + j] = fmaf(s, inv, ((float*)g_xr)[node * 64 + j]);
}

__global__ void k_gcnt() {
    int i = blockIdx.x * blockDim.x + threadIdx.x;
    if (i < NN) atomicAdd(&g_gcnt[g_batch[i]], 1.0f);
}

// pool: batch sorted -> strip-accumulate, atomics only at boundaries
__global__ void k_pool() {
    int t = blockIdx.x * blockDim.x + threadIdx.x;
    int strip = t >> 6, col = t & 63;
    int n0 = strip * STRIPN;
    int n1 = n0 + STRIPN; if (n1 > NN) n1 = NN;
    const float* hf = (const float*)g_h;
    int cur = -1; float sum = 0.f;
    for (int n = n0; n < n1; n++) {
        int b = g_batch[n];
        if (b != cur) {
            if (cur >= 0) atomicAdd(&g_pool[cur * DH + col], sum);
            cur = b; sum = 0.f;
        }
        sum += hf[n * 64 + col];
    }
    if (cur >= 0) atomicAdd(&g_pool[cur * DH + col], sum);
}

__global__ void k_pool_fin() {
    int i = blockIdx.x * blockDim.x + threadIdx.x;
    if (i < NG * DH)
        g_c[i] = g_pool[i] / fmaxf(g_gcnt[i >> 6], 1.0f);
}

__global__ void k_transpose(const float* __restrict__ W, float* __restrict__ Wt, int din) {
    int idx = blockIdx.x * blockDim.x + threadIdx.x;
    if (idx >= din * DH) return;
    int r = idx / DH, c = idx % DH;
    Wt[c * din + r] = W[idx];
}

__global__ void k_lin(const float* __restrict__ in, const float* __restrict__ W,
                      const float* __restrict__ b, float* __restrict__ out,
                      int din, int dout) {
    int r = blockIdx.x, j = threadIdx.x;
    extern __shared__ float rs[];
    for (int k = j; k < din; k += blockDim.x) rs[k] = in[r * din + k];
    __syncthreads();
    if (j >= dout) return;
    float s = b[j];
    for (int k = 0; k < din; k++) s = fmaf(rs[k], W[k * dout + j], s);
    out[r * dout + j] = s;
}

__global__ void k_bn_tanh(float* __restrict__ z, const float* __restrict__ gam,
                          const float* __restrict__ bet, int d) {
    int col = blockIdx.x, r = threadIdx.x;
    __shared__ float s1[NG], s2[NG];
    float v = z[r * d + col];
    s1[r] = v;
    __syncthreads();
    for (int o = NG / 2; o > 0; o >>= 1) {
        if (r < o) s1[r] += s1[r + o];
        __syncthreads();
    }
    float mean = s1[0] * (1.0f / NG);
    float dv = v - mean;
    s2[r] = dv * dv;
    __syncthreads();
    for (int o = NG / 2; o > 0; o >>= 1) {
        if (r < o) s2[r] += s2[r + o];
        __syncthreads();
    }
    float var = s2[0] * (1.0f / NG);
    z[r * d + col] = tanhf(dv * rsqrtf(var + EPSF) * gam[col] + bet[col]);
}

// ---------------- launch ----------------
extern "C" void kernel_launch(void* const* d_in, const int* in_sizes, int n_in,
                              void* d_out, int out_size) {
    const float* x     = (const float*)d_in[0];
    const void*  eidx  = d_in[1];
    const void*  batch = d_in[2];
    const float* W1l = (const float*)d_in[3];
    const float* b1l = (const float*)d_in[4];
    const float* W1r = (const float*)d_in[5];
    const float* W2l = (const float*)d_in[6];
    const float* b2l = (const float*)d_in[7];
    const float* W2r = (const float*)d_in[8];
    const float* W3l = (const float*)d_in[9];
    const float* b3l = (const float*)d_in[10];
    const float* W3r = (const float*)d_in[11];
    const float* lin1_w = (const float*)d_in[12];
    const float* lin1_b = (const float*)d_in[13];
    const float* g1  = (const float*)d_in[14];
    const float* be1 = (const float*)d_in[15];
    const float* lin2_w = (const float*)d_in[16];
    const float* lin2_b = (const float*)d_in[17];
    const float* g2  = (const float*)d_in[18];
    const float* be2 = (const float*)d_in[19];
    const float* lin3_w = (const float*)d_in[20];
    const float* lin3_b = (const float*)d_in[21];
    const float* g3  = (const float*)d_in[22];
    const float* be3 = (const float*)d_in[23];
    const float* lin4_w = (const float*)d_in[24];
    const float* lin4_b = (const float*)d_in[25];

    void *p_deg, *p_pool, *p_gcnt, *p_Wt, *p_c, *p_z1, *p_z2, *p_z3, *p_h;
    cudaGetSymbolAddress(&p_deg,  g_deg);
    cudaGetSymbolAddress(&p_pool, g_pool);
    cudaGetSymbolAddress(&p_gcnt, g_gcnt);
    cudaGetSymbolAddress(&p_Wt,   g_Wt);
    cudaGetSymbolAddress(&p_c,    g_c);
    cudaGetSymbolAddress(&p_z1,   g_z1);
    cudaGetSymbolAddress(&p_z2,   g_z2);
    cudaGetSymbolAddress(&p_z3,   g_z3);
    cudaGetSymbolAddress(&p_h,    g_h);

    float4* Wt = (float4*)p_Wt;
    const int TB = 256;

    // ---- dtype detect + CSR build ----
    k_detect<<<1, 32>>>((const int*)eidx);
    k_zeroi<<<(NN + TB - 1)/TB, TB>>>((int*)p_deg, NN);
    k_prep <<<(NE + TB - 1)/TB, TB>>>(eidx);
    k_bconv<<<(NN + TB - 1)/TB, TB>>>(batch);
    k_scan1<<<NBLK, SBS>>>();
    k_scan2<<<1, 32>>>();
    k_scan3<<<(NN + TB)/TB, TB>>>();
    k_fill <<<(NE + TB - 1)/TB, TB>>>();

    // ---- weight transposes ----
    k_transpose<<<(128*DH + TB - 1)/TB, TB>>>(W1l, (float*)(Wt + 0*2048), 128);
    k_transpose<<<(128*DH + TB - 1)/TB, TB>>>(W1r, (float*)(Wt + 1*2048), 128);
    k_transpose<<<( 64*DH + TB - 1)/TB, TB>>>(W2l, (float*)(Wt + 2*2048), 64);
    k_transpose<<<( 64*DH + TB - 1)/TB, TB>>>(W2r, (float*)(Wt + 3*2048), 64);
    k_transpose<<<( 64*DH + TB - 1)/TB, TB>>>(W3l, (float*)(Wt + 4*2048), 64);
    k_transpose<<<( 64*DH + TB - 1)/TB, TB>>>(W3r, (float*)(Wt + 5*2048), 64);

    // ---- 3 SAGE layers: transform-then-aggregate ----
    k_dual_gemm<<<NN/4, TB>>>(x, Wt + 0*2048, Wt + 1*2048, b1l, 128);
    k_aggr<<<NN/4, TB>>>();
    k_dual_gemm<<<NN/4, TB>>>((const float*)p_h, Wt + 2*2048, Wt + 3*2048, b2l, 64);
    k_aggr<<<NN/4, TB>>>();
    k_dual_gemm<<<NN/4, TB>>>((const float*)p_h, Wt + 4*2048, Wt + 5*2048, b3l, 64);
    k_aggr<<<NN/4, TB>>>();

    // ---- pool ----
    k_zero<<<(NG*DH + TB - 1)/TB, TB>>>((float*)p_pool, NG*DH);
    k_zero<<<1, TB>>>((float*)p_gcnt, NG);
    k_gcnt<<<(NN + TB - 1)/TB, TB>>>();
    k_pool<<<(NSTRIP*64)/TB, TB>>>();
    k_pool_fin<<<(NG*DH + TB - 1)/TB, TB>>>();

    // ---- MLP head ----
    float* c  = (float*)p_c;
    float* z1 = (float*)p_z1;
    float* z2 = (float*)p_z2;
    float* z3 = (float*)p_z3;
    k_lin<<<NG, 256, DH*sizeof(float)>>>(c, lin1_w, lin1_b, z1, DH, HID);
    k_bn_tanh<<<HID, NG>>>(z1, g1, be1, HID);
    k_lin<<<NG, 128, HID*sizeof(float)>>>(z1, lin2_w, lin2_b, z2, HID, HID/2);
    k_bn_tanh<<<HID/2, NG>>>(z2, g2, be2, HID/2);
    k_lin<<<NG, 64, (HID/2)*sizeof(float)>>>(z2, lin3_w, lin3_b, z3, HID/2, HID/4);
    k_bn_tanh<<<HID/4, NG>>>(z3, g3, be3, HID/4);
    k_lin<<<NG, 32, (HID/4)*sizeof(float)>>>(z3, lin4_w, lin4_b, (float*)d_out, HID/4, 10);
}

// round 5
// speedup vs baseline: 3.7632x; 3.7632x over previous
#include <cuda_runtime.h>

#define NN 50000
#define NE 800000
#define NG 256
#define DH  64
#define HID 256
#define EPSF 1e-5f
#define SBS 256
#define NBLK ((NN + SBS - 1) / SBS)          // 196
#define NSTRIP 128
#define STRIPN ((NN + NSTRIP - 1) / NSTRIP)  // 391

// ---------------- device scratch ----------------
__device__ float4 g_xl [NN*16];
__device__ float4 g_xr [NN*16];
__device__ float4 g_h  [NN*16];
__device__ float  g_pool[NG*DH];
__device__ float  g_gcnt[NG];
__device__ float  g_c  [NG*DH];
__device__ float  g_z1 [NG*HID];
__device__ float  g_z2 [NG*(HID/2)];
__device__ float  g_z3 [NG*(HID/4)];
__device__ int    g_src[NE];
__device__ int    g_dst[NE];
__device__ int    g_batch[NN];
__device__ int    g_deg[NN];
__device__ int    g_part[NN];
__device__ int    g_bsum[NBLK];
__device__ int    g_boff[NBLK];
__device__ int    g_rowptr[NN + 1];
__device__ int    g_woff[NN];
__device__ int    g_csr[NE];
__device__ int    g_is64;

// ---------------- kernels ----------------
__global__ void k_zero(float* __restrict__ p, int n) {
    int i = blockIdx.x * blockDim.x + threadIdx.x;
    if (i < n) p[i] = 0.f;
}
__global__ void k_zeroi(int* __restrict__ p, int n) {
    int i = blockIdx.x * blockDim.x + threadIdx.x;
    if (i < n) p[i] = 0;
}

// int64 vs int32 detect: int64 node ids (<2^31) have zero high words.
__global__ void k_detect(const int* __restrict__ e32) {
    if (threadIdx.x == 0 && blockIdx.x == 0) {
        int all0 = 1;
        for (int k = 0; k < 16; k++)
            if (e32[2 * (1000 + k) + 1] != 0) all0 = 0;
        g_is64 = all0;
    }
}

__global__ void k_prep(const void* __restrict__ eidx) {
    int e = blockIdx.x * blockDim.x + threadIdx.x;
    if (e >= NE) return;
    int s, d;
    if (g_is64) {
        const long long* p = (const long long*)eidx;
        s = (int)p[e];
        d = (int)p[NE + e];
    } else {
        const int* p = (const int*)eidx;
        s = p[e];
        d = p[NE + e];
    }
    g_src[e] = s;
    g_dst[e] = d;
    atomicAdd(&g_deg[d], 1);
}

__global__ void k_bconv(const void* __restrict__ batch) {
    int i = blockIdx.x * blockDim.x + threadIdx.x;
    if (i >= NN) return;
    g_batch[i] = g_is64 ? (int)((const long long*)batch)[i]
                        : ((const int*)batch)[i];
}

__global__ void k_scan1() {
    __shared__ int s[SBS];
    int tid = threadIdx.x;
    int i = blockIdx.x * SBS + tid;
    int v = (i < NN) ? g_deg[i] : 0;
    s[tid] = v;
    __syncthreads();
    for (int off = 1; off < SBS; off <<= 1) {
        int t = (tid >= off) ? s[tid - off] : 0;
        __syncthreads();
        s[tid] += t;
        __syncthreads();
    }
    if (i < NN) g_part[i] = s[tid] - v;
    if (tid == SBS - 1) g_bsum[blockIdx.x] = s[tid];
}

__global__ void k_scan2() {
    if (threadIdx.x == 0 && blockIdx.x == 0) {
        int run = 0;
        for (int b = 0; b < NBLK; b++) {
            g_boff[b] = run;
            run += g_bsum[b];
        }
    }
}

__global__ void k_scan3() {
    int i = blockIdx.x * blockDim.x + threadIdx.x;
    if (i < NN) {
        int r = g_part[i] + g_boff[i / SBS];
        g_rowptr[i] = r;
        g_woff[i]   = r;
    }
    if (i == 0) g_rowptr[NN] = NE;
}

__global__ void k_fill() {
    int e = blockIdx.x * blockDim.x + threadIdx.x;
    if (e >= NE) return;
    int d = g_dst[e];
    int p = atomicAdd(&g_woff[d], 1);
    g_csr[p] = g_src[e];
}

// Dual GEMM, NATIVE weight layout W[k][j] (coalesced over j).
// Block = 16 nodes, 256 threads: j = tid&63 (output col), g = tid>>6.
// Each thread computes 4 nodes x 1 col for both Wl and Wr (weights reused 4x).
__global__ void k_dual_gemm(const float* __restrict__ x,
                            const float* __restrict__ Wl,   // [din,64]
                            const float* __restrict__ Wr,   // [din,64]
                            const float* __restrict__ bl, int din) {
    __shared__ float xs[16 * 128];
    int tid = threadIdx.x;
    int j = tid & 63, g = tid >> 6;
    int nbase = blockIdx.x * 16;
    // cooperative coalesced load of 16 node rows
    for (int idx = tid; idx < 16 * din; idx += 256)
        xs[idx] = x[nbase * din + idx];
    __syncthreads();

    const float* r0 = xs + (g * 4 + 0) * din;
    const float* r1 = xs + (g * 4 + 1) * din;
    const float* r2 = xs + (g * 4 + 2) * din;
    const float* r3 = xs + (g * 4 + 3) * din;

    float a0=0.f,a1=0.f,a2=0.f,a3=0.f;
    float c0=0.f,c1=0.f,c2=0.f,c3=0.f;
#pragma unroll 4
    for (int k = 0; k < din; k++) {
        float wl = Wl[k * 64 + j];
        float wr = Wr[k * 64 + j];
        float x0 = r0[k], x1 = r1[k], x2 = r2[k], x3 = r3[k];
        a0 = fmaf(wl, x0, a0); a1 = fmaf(wl, x1, a1);
        a2 = fmaf(wl, x2, a2); a3 = fmaf(wl, x3, a3);
        c0 = fmaf(wr, x0, c0); c1 = fmaf(wr, x1, c1);
        c2 = fmaf(wr, x2, c2); c3 = fmaf(wr, x3, c3);
    }
    float b = bl[j];
    float* xlf = (float*)g_xl;
    float* xrf = (float*)g_xr;
    int n = nbase + g * 4;
    xlf[(n+0)*64 + j] = a0; xrf[(n+0)*64 + j] = c0 + b;
    xlf[(n+1)*64 + j] = a1; xrf[(n+1)*64 + j] = c1 + b;
    xlf[(n+2)*64 + j] = a2; xrf[(n+2)*64 + j] = c2 + b;
    xlf[(n+3)*64 + j] = a3; xrf[(n+3)*64 + j] = c3 + b;
}

// CSR gather aggregation: h = mean_in(xl) + xr (64 threads/node, 4-way unroll)
__global__ void k_aggr() {
    int node = blockIdx.x * 4 + (threadIdx.x >> 6);
    int j    = threadIdx.x & 63;
    int beg = g_rowptr[node], end = g_rowptr[node + 1];
    const float* xlf = (const float*)g_xl;
    float s = 0.f;
    int i = beg;
    for (; i + 3 < end; i += 4) {
        int u0 = g_csr[i], u1 = g_csr[i+1], u2 = g_csr[i+2], u3 = g_csr[i+3];
        float v0 = xlf[u0*64 + j], v1 = xlf[u1*64 + j];
        float v2 = xlf[u2*64 + j], v3 = xlf[u3*64 + j];
        s += (v0 + v1) + (v2 + v3);
    }
    for (; i < end; i++) s += xlf[g_csr[i]*64 + j];
    float inv = 1.0f / fmaxf((float)(end - beg), 1.0f);
    ((float*)g_h)[node * 64 + j] = fmaf(s, inv, ((float*)g_xr)[node * 64 + j]);
}

__global__ void k_gcnt() {
    int i = blockIdx.x * blockDim.x + threadIdx.x;
    if (i < NN) atomicAdd(&g_gcnt[g_batch[i]], 1.0f);
}

__global__ void k_pool() {
    int t = blockIdx.x * blockDim.x + threadIdx.x;
    int strip = t >> 6, col = t & 63;
    int n0 = strip * STRIPN;
    int n1 = n0 + STRIPN; if (n1 > NN) n1 = NN;
    const float* hf = (const float*)g_h;
    int cur = -1; float sum = 0.f;
    for (int n = n0; n < n1; n++) {
        int b = g_batch[n];
        if (b != cur) {
            if (cur >= 0) atomicAdd(&g_pool[cur * DH + col], sum);
            cur = b; sum = 0.f;
        }
        sum += hf[n * 64 + col];
    }
    if (cur >= 0) atomicAdd(&g_pool[cur * DH + col], sum);
}

__global__ void k_pool_fin() {
    int i = blockIdx.x * blockDim.x + threadIdx.x;
    if (i < NG * DH)
        g_c[i] = g_pool[i] / fmaxf(g_gcnt[i >> 6], 1.0f);
}

__global__ void k_lin(const float* __restrict__ in, const float* __restrict__ W,
                      const float* __restrict__ b, float* __restrict__ out,
                      int din, int dout) {
    int r = blockIdx.x, j = threadIdx.x;
    extern __shared__ float rs[];
    for (int k = j; k < din; k += blockDim.x) rs[k] = in[r * din + k];
    __syncthreads();
    if (j >= dout) return;
    float s = b[j];
    for (int k = 0; k < din; k++) s = fmaf(rs[k], W[k * dout + j], s);
    out[r * dout + j] = s;
}

__global__ void k_bn_tanh(float* __restrict__ z, const float* __restrict__ gam,
                          const float* __restrict__ bet, int d) {
    int col = blockIdx.x, r = threadIdx.x;
    __shared__ float s1[NG], s2[NG];
    float v = z[r * d + col];
    s1[r] = v;
    __syncthreads();
    for (int o = NG / 2; o > 0; o >>= 1) {
        if (r < o) s1[r] += s1[r + o];
        __syncthreads();
    }
    float mean = s1[0] * (1.0f / NG);
    float dv = v - mean;
    s2[r] = dv * dv;
    __syncthreads();
    for (int o = NG / 2; o > 0; o >>= 1) {
        if (r < o) s2[r] += s2[r + o];
        __syncthreads();
    }
    float var = s2[0] * (1.0f / NG);
    z[r * d + col] = tanhf(dv * rsqrtf(var + EPSF) * gam[col] + bet[col]);
}

// ---------------- launch ----------------
extern "C" void kernel_launch(void* const* d_in, const int* in_sizes, int n_in,
                              void* d_out, int out_size) {
    const float* x     = (const float*)d_in[0];
    const void*  eidx  = d_in[1];
    const void*  batch = d_in[2];
    const float* W1l = (const float*)d_in[3];
    const float* b1l = (const float*)d_in[4];
    const float* W1r = (const float*)d_in[5];
    const float* W2l = (const float*)d_in[6];
    const float* b2l = (const float*)d_in[7];
    const float* W2r = (const float*)d_in[8];
    const float* W3l = (const float*)d_in[9];
    const float* b3l = (const float*)d_in[10];
    const float* W3r = (const float*)d_in[11];
    const float* lin1_w = (const float*)d_in[12];
    const float* lin1_b = (const float*)d_in[13];
    const float* g1  = (const float*)d_in[14];
    const float* be1 = (const float*)d_in[15];
    const float* lin2_w = (const float*)d_in[16];
    const float* lin2_b = (const float*)d_in[17];
    const float* g2  = (const float*)d_in[18];
    const float* be2 = (const float*)d_in[19];
    const float* lin3_w = (const float*)d_in[20];
    const float* lin3_b = (const float*)d_in[21];
    const float* g3  = (const float*)d_in[22];
    const float* be3 = (const float*)d_in[23];
    const float* lin4_w = (const float*)d_in[24];
    const float* lin4_b = (const float*)d_in[25];

    void *p_deg, *p_pool, *p_gcnt, *p_c, *p_z1, *p_z2, *p_z3, *p_h;
    cudaGetSymbolAddress(&p_deg,  g_deg);
    cudaGetSymbolAddress(&p_pool, g_pool);
    cudaGetSymbolAddress(&p_gcnt, g_gcnt);
    cudaGetSymbolAddress(&p_c,    g_c);
    cudaGetSymbolAddress(&p_z1,   g_z1);
    cudaGetSymbolAddress(&p_z2,   g_z2);
    cudaGetSymbolAddress(&p_z3,   g_z3);
    cudaGetSymbolAddress(&p_h,    g_h);

    const int TB = 256;

    // launches 1-5
    k_detect<<<1, 32>>>((const int*)eidx);
    k_zeroi<<<(NN + TB - 1)/TB, TB>>>((int*)p_deg, NN);
    k_prep <<<(NE + TB - 1)/TB, TB>>>(eidx);
    k_bconv<<<(NN + TB - 1)/TB, TB>>>(batch);
    k_scan1<<<NBLK, SBS>>>();

    // launch 6 = layer-1 GEMM (ncu -s 5 -c 1 captures this one)
    k_dual_gemm<<<NN/16, TB>>>(x, W1l, W1r, b1l, 128);

    // finish CSR build
    k_scan2<<<1, 32>>>();
    k_scan3<<<(NN + TB)/TB, TB>>>();
    k_fill <<<(NE + TB - 1)/TB, TB>>>();

    // layer 1 aggregate, then layers 2-3
    k_aggr<<<NN/4, TB>>>();
    k_dual_gemm<<<NN/16, TB>>>((const float*)p_h, W2l, W2r, b2l, 64);
    k_aggr<<<NN/4, TB>>>();
    k_dual_gemm<<<NN/16, TB>>>((const float*)p_h, W3l, W3r, b3l, 64);
    k_aggr<<<NN/4, TB>>>();

    // pool
    k_zero<<<(NG*DH + TB - 1)/TB, TB>>>((float*)p_pool, NG*DH);
    k_zero<<<1, TB>>>((float*)p_gcnt, NG);
    k_gcnt<<<(NN + TB - 1)/TB, TB>>>();
    k_pool<<<(NSTRIP*64)/TB, TB>>>();
    k_pool_fin<<<(NG*DH + TB - 1)/TB, TB>>>();

    // MLP head
    float* c  = (float*)p_c;
    float* z1 = (float*)p_z1;
    float* z2 = (float*)p_z2;
    float* z3 = (float*)p_z3;
    k_lin<<<NG, 256, DH*sizeof(float)>>>(c, lin1_w, lin1_b, z1, DH, HID);
    k_bn_tanh<<<HID, NG>>>(z1, g1, be1, HID);
    k_lin<<<NG, 128, HID*sizeof(float)>>>(z1, lin2_w, lin2_b, z2, HID, HID/2);
    k_bn_tanh<<<HID/2, NG>>>(z2, g2, be2, HID/2);
    k_lin<<<NG, 64, (HID/2)*sizeof(float)>>>(z2, lin3_w, lin3_b, z3, HID/2, HID/4);
    k_bn_tanh<<<HID/4, NG>>>(z3, g3, be3, HID/4);
    k_lin<<<NG, 32, (HID/4)*sizeof(float)>>>(z3, lin4_w, lin4_b, (float*)d_out, HID/4, 10);
}

// round 7
// speedup vs baseline: 3.9577x; 1.0517x over previous
#include <cuda_runtime.h>

#define NN 50000
#define NE 800000
#define NG 256
#define DH  64
#define HID 256
#define EPSF 1e-5f
#define SBS 256
#define NBLK ((NN + SBS - 1) / SBS)          // 196
#define NSTRIP 128
#define STRIPN ((NN + NSTRIP - 1) / NSTRIP)  // 391

// ---------------- device scratch ----------------
__device__ float4 g_xl [NN*16];
__device__ float4 g_xr [NN*16];
__device__ float4 g_h  [NN*16];
__device__ float  g_pool[NG*DH];
__device__ float  g_gcnt[NG];
__device__ float  g_c  [NG*DH];
__device__ float  g_z1 [NG*HID];
__device__ float  g_z2 [NG*(HID/2)];
__device__ float  g_z3 [NG*(HID/4)];
__device__ int    g_src[NE];
__device__ int    g_dst[NE];
__device__ int    g_batch[NN];
__device__ int    g_deg[NN];
__device__ int    g_part[NN];
__device__ int    g_bsum[NBLK];
__device__ int    g_boff[NBLK];
__device__ int    g_rowptr[NN + 1];
__device__ int    g_woff[NN];
__device__ int    g_csr[NE];
__device__ int    g_is64;

// ---------------- small kernels ----------------
__global__ void k_zero(float* __restrict__ p, int n) {
    int i = blockIdx.x * blockDim.x + threadIdx.x;
    if (i < n) p[i] = 0.f;
}
__global__ void k_zeroi(int* __restrict__ p, int n) {
    int i = blockIdx.x * blockDim.x + threadIdx.x;
    if (i < n) p[i] = 0;
}

__global__ void k_detect(const int* __restrict__ e32) {
    if (threadIdx.x == 0 && blockIdx.x == 0) {
        int all0 = 1;
        for (int k = 0; k < 16; k++)
            if (e32[2 * (1000 + k) + 1] != 0) all0 = 0;
        g_is64 = all0;
    }
}

__global__ void k_prep(const void* __restrict__ eidx) {
    int e = blockIdx.x * blockDim.x + threadIdx.x;
    if (e >= NE) return;
    int s, d;
    if (g_is64) {
        const long long* p = (const long long*)eidx;
        s = (int)p[e];
        d = (int)p[NE + e];
    } else {
        const int* p = (const int*)eidx;
        s = p[e];
        d = p[NE + e];
    }
    g_src[e] = s;
    g_dst[e] = d;
    atomicAdd(&g_deg[d], 1);
}

__global__ void k_bconv(const void* __restrict__ batch) {
    int i = blockIdx.x * blockDim.x + threadIdx.x;
    if (i >= NN) return;
    g_batch[i] = g_is64 ? (int)((const long long*)batch)[i]
                        : ((const int*)batch)[i];
}

__global__ void k_scan1() {
    __shared__ int s[SBS];
    int tid = threadIdx.x;
    int i = blockIdx.x * SBS + tid;
    int v = (i < NN) ? g_deg[i] : 0;
    s[tid] = v;
    __syncthreads();
    for (int off = 1; off < SBS; off <<= 1) {
        int t = (tid >= off) ? s[tid - off] : 0;
        __syncthreads();
        s[tid] += t;
        __syncthreads();
    }
    if (i < NN) g_part[i] = s[tid] - v;
    if (tid == SBS - 1) g_bsum[blockIdx.x] = s[tid];
}

__global__ void k_scan2() {
    if (threadIdx.x == 0 && blockIdx.x == 0) {
        int run = 0;
        for (int b = 0; b < NBLK; b++) {
            g_boff[b] = run;
            run += g_bsum[b];
        }
    }
}

__global__ void k_scan3() {
    int i = blockIdx.x * blockDim.x + threadIdx.x;
    if (i < NN) {
        int r = g_part[i] + g_boff[i / SBS];
        g_rowptr[i] = r;
        g_woff[i]   = r;
    }
    if (i == 0) g_rowptr[NN] = NE;
}

__global__ void k_fill() {
    int e = blockIdx.x * blockDim.x + threadIdx.x;
    if (e >= NE) return;
    int d = g_dst[e];
    int p = atomicAdd(&g_woff[d], 1);
    g_csr[p] = g_src[e];
}

// Dual GEMM: 64 nodes/block, 256 threads.
// Thread tile = 4 nodes x 4 cols per matrix.
// Per k: 2x LDG.128 (Wl,Wr rows, coalesced) + 4x LDS (broadcast) + 32 FMA.
__global__ void k_dual_gemm(const float* __restrict__ x,
                            const float* __restrict__ Wl,   // [din,64]
                            const float* __restrict__ Wr,   // [din,64]
                            const float* __restrict__ bl, int din) {
    __shared__ float xs[64 * 128];
    int tid = threadIdx.x;
    int j4 = tid & 15;          // col group: cols j4*4 .. j4*4+3
    int g  = tid >> 4;          // node group: 4 nodes
    int nbase = blockIdx.x * 64;

    int tot = 64 * din;
    int gbase = nbase * din;
    int gmax  = NN * din;
    for (int idx = tid; idx < tot; idx += 256) {
        int gi = gbase + idx;
        xs[idx] = (gi < gmax) ? x[gi] : 0.f;
    }
    __syncthreads();

    const float* r0 = xs + (g * 4 + 0) * din;
    const float* r1 = xs + (g * 4 + 1) * din;
    const float* r2 = xs + (g * 4 + 2) * din;
    const float* r3 = xs + (g * 4 + 3) * din;

    float4 a0 = {0,0,0,0}, a1 = {0,0,0,0}, a2 = {0,0,0,0}, a3 = {0,0,0,0};
    float4 c0 = {0,0,0,0}, c1 = {0,0,0,0}, c2 = {0,0,0,0}, c3 = {0,0,0,0};

#pragma unroll 4
    for (int k = 0; k < din; k++) {
        float4 wl = *(const float4*)(Wl + k * 64 + j4 * 4);
        float4 wr = *(const float4*)(Wr + k * 64 + j4 * 4);
        float x0 = r0[k], x1 = r1[k], x2 = r2[k], x3 = r3[k];
        a0.x = fmaf(wl.x, x0, a0.x); a0.y = fmaf(wl.y, x0, a0.y);
        a0.z = fmaf(wl.z, x0, a0.z); a0.w = fmaf(wl.w, x0, a0.w);
        a1.x = fmaf(wl.x, x1, a1.x); a1.y = fmaf(wl.y, x1, a1.y);
        a1.z = fmaf(wl.z, x1, a1.z); a1.w = fmaf(wl.w, x1, a1.w);
        a2.x = fmaf(wl.x, x2, a2.x); a2.y = fmaf(wl.y, x2, a2.y);
        a2.z = fmaf(wl.z, x2, a2.z); a2.w = fmaf(wl.w, x2, a2.w);
        a3.x = fmaf(wl.x, x3, a3.x); a3.y = fmaf(wl.y, x3, a3.y);
        a3.z = fmaf(wl.z, x3, a3.z); a3.w = fmaf(wl.w, x3, a3.w);
        c0.x = fmaf(wr.x, x0, c0.x); c0.y = fmaf(wr.y, x0, c0.y);
        c0.z = fmaf(wr.z, x0, c0.z); c0.w = fmaf(wr.w, x0, c0.w);
        c1.x = fmaf(wr.x, x1, c1.x); c1.y = fmaf(wr.y, x1, c1.y);
        c1.z = fmaf(wr.z, x1, c1.z); c1.w = fmaf(wr.w, x1, c1.w);
        c2.x = fmaf(wr.x, x2, c2.x); c2.y = fmaf(wr.y, x2, c2.y);
        c2.z = fmaf(wr.z, x2, c2.z); c2.w = fmaf(wr.w, x2, c2.w);
        c3.x = fmaf(wr.x, x3, c3.x); c3.y = fmaf(wr.y, x3, c3.y);
        c3.z = fmaf(wr.z, x3, c3.z); c3.w = fmaf(wr.w, x3, c3.w);
    }

    float4 b = *(const float4*)(bl + j4 * 4);
    c0.x += b.x; c0.y += b.y; c0.z += b.z; c0.w += b.w;
    c1.x += b.x; c1.y += b.y; c1.z += b.z; c1.w += b.w;
    c2.x += b.x; c2.y += b.y; c2.z += b.z; c2.w += b.w;
    c3.x += b.x; c3.y += b.y; c3.z += b.z; c3.w += b.w;

    int n = nbase + g * 4;
    if (n + 3 < NN) {
        g_xl[(n+0)*16 + j4] = a0; g_xr[(n+0)*16 + j4] = c0;
        g_xl[(n+1)*16 + j4] = a1; g_xr[(n+1)*16 + j4] = c1;
        g_xl[(n+2)*16 + j4] = a2; g_xr[(n+2)*16 + j4] = c2;
        g_xl[(n+3)*16 + j4] = a3; g_xr[(n+3)*16 + j4] = c3;
    } else {
        if (n+0 < NN) { g_xl[(n+0)*16 + j4] = a0; g_xr[(n+0)*16 + j4] = c0; }
        if (n+1 < NN) { g_xl[(n+1)*16 + j4] = a1; g_xr[(n+1)*16 + j4] = c1; }
        if (n+2 < NN) { g_xl[(n+2)*16 + j4] = a2; g_xr[(n+2)*16 + j4] = c2; }
        if (n+3 < NN) { g_xl[(n+3)*16 + j4] = a3; g_xr[(n+3)*16 + j4] = c3; }
    }
}

// CSR gather aggregation in float4: 16 threads/node (q = 4-col group).
// h = mean_in(xl) + xr
__global__ void k_aggr() {
    int node = blockIdx.x * 16 + (threadIdx.x >> 4);
    int q    = threadIdx.x & 15;
    int beg = g_rowptr[node], end = g_rowptr[node + 1];
    float4 s = {0,0,0,0};
    int i = beg;
    for (; i + 3 < end; i += 4) {
        int u0 = g_csr[i], u1 = g_csr[i+1], u2 = g_csr[i+2], u3 = g_csr[i+3];
        float4 v0 = g_xl[u0*16 + q];
        float4 v1 = g_xl[u1*16 + q];
        float4 v2 = g_xl[u2*16 + q];
        float4 v3 = g_xl[u3*16 + q];
        s.x += (v0.x + v1.x) + (v2.x + v3.x);
        s.y += (v0.y + v1.y) + (v2.y + v3.y);
        s.z += (v0.z + v1.z) + (v2.z + v3.z);
        s.w += (v0.w + v1.w) + (v2.w + v3.w);
    }
    for (; i < end; i++) {
        float4 v = g_xl[g_csr[i]*16 + q];
        s.x += v.x; s.y += v.y; s.z += v.z; s.w += v.w;
    }
    float inv = 1.0f / fmaxf((float)(end - beg), 1.0f);
    float4 r = g_xr[node*16 + q];
    float4 o;
    o.x = fmaf(s.x, inv, r.x);
    o.y = fmaf(s.y, inv, r.y);
    o.z = fmaf(s.z, inv, r.z);
    o.w = fmaf(s.w, inv, r.w);
    g_h[node*16 + q] = o;
}

__global__ void k_gcnt() {
    int i = blockIdx.x * blockDim.x + threadIdx.x;
    if (i < NN) atomicAdd(&g_gcnt[g_batch[i]], 1.0f);
}

__global__ void k_pool() {
    int t = blockIdx.x * blockDim.x + threadIdx.x;
    int strip = t >> 6, col = t & 63;
    int n0 = strip * STRIPN;
    int n1 = n0 + STRIPN; if (n1 > NN) n1 = NN;
    const float* hf = (const float*)g_h;
    int cur = -1; float sum = 0.f;
    for (int n = n0; n < n1; n++) {
        int b = g_batch[n];
        if (b != cur) {
            if (cur >= 0) atomicAdd(&g_pool[cur * DH + col], sum);
            cur = b; sum = 0.f;
        }
        sum += hf[n * 64 + col];
    }
    if (cur >= 0) atomicAdd(&g_pool[cur * DH + col], sum);
}

__global__ void k_pool_fin() {
    int i = blockIdx.x * blockDim.x + threadIdx.x;
    if (i < NG * DH)
        g_c[i] = g_pool[i] / fmaxf(g_gcnt[i >> 6], 1.0f);
}

__global__ void k_lin(const float* __restrict__ in, const float* __restrict__ W,
                      const float* __restrict__ b, float* __restrict__ out,
                      int din, int dout) {
    int r = blockIdx.x, j = threadIdx.x;
    extern __shared__ float rs[];
    for (int k = j; k < din; k += blockDim.x) rs[k] = in[r * din + k];
    __syncthreads();
    if (j >= dout) return;
    float s = b[j];
    for (int k = 0; k < din; k++) s = fmaf(rs[k], W[k * dout + j], s);
    out[r * dout + j] = s;
}

__global__ void k_bn_tanh(float* __restrict__ z, const float* __restrict__ gam,
                          const float* __restrict__ bet, int d) {
    int col = blockIdx.x, r = threadIdx.x;
    __shared__ float s1[NG], s2[NG];
    float v = z[r * d + col];
    s1[r] = v;
    __syncthreads();
    for (int o = NG / 2; o > 0; o >>= 1) {
        if (r < o) s1[r] += s1[r + o];
        __syncthreads();
    }
    float mean = s1[0] * (1.0f / NG);
    float dv = v - mean;
    s2[r] = dv * dv;
    __syncthreads();
    for (int o = NG / 2; o > 0; o >>= 1) {
        if (r < o) s2[r] += s2[r + o];
        __syncthreads();
    }
    float var = s2[0] * (1.0f / NG);
    z[r * d + col] = tanhf(dv * rsqrtf(var + EPSF) * gam[col] + bet[col]);
}

// ---------------- launch ----------------
extern "C" void kernel_launch(void* const* d_in, const int* in_sizes, int n_in,
                              void* d_out, int out_size) {
    const float* x     = (const float*)d_in[0];
    const void*  eidx  = d_in[1];
    const void*  batch = d_in[2];
    const float* W1l = (const float*)d_in[3];
    const float* b1l = (const float*)d_in[4];
    const float* W1r = (const float*)d_in[5];
    const float* W2l = (const float*)d_in[6];
    const float* b2l = (const float*)d_in[7];
    const float* W2r = (const float*)d_in[8];
    const float* W3l = (const float*)d_in[9];
    const float* b3l = (const float*)d_in[10];
    const float* W3r = (const float*)d_in[11];
    const float* lin1_w = (const float*)d_in[12];
    const float* lin1_b = (const float*)d_in[13];
    const float* g1  = (const float*)d_in[14];
    const float* be1 = (const float*)d_in[15];
    const float* lin2_w = (const float*)d_in[16];
    const float* lin2_b = (const float*)d_in[17];
    const float* g2  = (const float*)d_in[18];
    const float* be2 = (const float*)d_in[19];
    const float* lin3_w = (const float*)d_in[20];
    const float* lin3_b = (const float*)d_in[21];
    const float* g3  = (const float*)d_in[22];
    const float* be3 = (const float*)d_in[23];
    const float* lin4_w = (const float*)d_in[24];
    const float* lin4_b = (const float*)d_in[25];

    void *p_deg, *p_pool, *p_gcnt, *p_c, *p_z1, *p_z2, *p_z3, *p_h;
    cudaGetSymbolAddress(&p_deg,  g_deg);
    cudaGetSymbolAddress(&p_pool, g_pool);
    cudaGetSymbolAddress(&p_gcnt, g_gcnt);
    cudaGetSymbolAddress(&p_c,    g_c);
    cudaGetSymbolAddress(&p_z1,   g_z1);
    cudaGetSymbolAddress(&p_z2,   g_z2);
    cudaGetSymbolAddress(&p_z3,   g_z3);
    cudaGetSymbolAddress(&p_h,    g_h);

    const int TB = 256;
    const int GEMM_BLK = (NN + 63) / 64;   // 782

    // dtype detect + CSR build start
    k_detect<<<1, 32>>>((const int*)eidx);
    k_zeroi<<<(NN + TB - 1)/TB, TB>>>((int*)p_deg, NN);
    k_prep <<<(NE + TB - 1)/TB, TB>>>(eidx);
    k_bconv<<<(NN + TB - 1)/TB, TB>>>(batch);
    k_scan1<<<NBLK, SBS>>>();

    // layer-1 GEMM (independent of CSR build)
    k_dual_gemm<<<GEMM_BLK, TB>>>(x, W1l, W1r, b1l, 128);

    // finish CSR build
    k_scan2<<<1, 32>>>();
    k_scan3<<<(NN + TB)/TB, TB>>>();
    k_fill <<<(NE + TB - 1)/TB, TB>>>();

    // layer 1 aggregate, then layers 2-3
    k_aggr<<<NN/16, TB>>>();
    k_dual_gemm<<<GEMM_BLK, TB>>>((const float*)p_h, W2l, W2r, b2l, 64);
    k_aggr<<<NN/16, TB>>>();
    k_dual_gemm<<<GEMM_BLK, TB>>>((const float*)p_h, W3l, W3r, b3l, 64);
    k_aggr<<<NN/16, TB>>>();

    // pool
    k_zero<<<(NG*DH + TB - 1)/TB, TB>>>((float*)p_pool, NG*DH);
    k_zero<<<1, TB>>>((float*)p_gcnt, NG);
    k_gcnt<<<(NN + TB - 1)/TB, TB>>>();
    k_pool<<<(NSTRIP*64)/TB, TB>>>();
    k_pool_fin<<<(NG*DH + TB - 1)/TB, TB>>>();

    // MLP head
    float* c  = (float*)p_c;
    float* z1 = (float*)p_z1;
    float* z2 = (float*)p_z2;
    float* z3 = (float*)p_z3;
    k_lin<<<NG, 256, DH*sizeof(float)>>>(c, lin1_w, lin1_b, z1, DH, HID);
    k_bn_tanh<<<HID, NG>>>(z1, g1, be1, HID);
    k_lin<<<NG, 128, HID*sizeof(float)>>>(z1, lin2_w, lin2_b, z2, HID, HID/2);
    k_bn_tanh<<<HID/2, NG>>>(z2, g2, be2, HID/2);
    k_lin<<<NG, 64, (HID/2)*sizeof(float)>>>(z2, lin3_w, lin3_b, z3, HID/2, HID/4);
    k_bn_tanh<<<HID/4, NG>>>(z3, g3, be3, HID/4);
    k_lin<<<NG, 32, (HID/4)*sizeof(float)>>>(z3, lin4_w, lin4_b, (float*)d_out, HID/4, 10);
}